// round 16
// baseline (speedup 1.0000x reference)
#include <cuda_runtime.h>
#include <cuda_fp16.h>
#include <math.h>
#include <stdint.h>

#define NTOK   8192
#define DMODEL 768
#define DFFN   3072
#define NH     12
#define DHD    64
#define SEQ    1024
#define NBATCH 8
#define LN_EPS 1e-6f

// ---------------- scratch (static device globals; no allocation) ----------------
__device__ half  g_xh [NTOK * DMODEL];
__device__ half  g_x1h[NTOK * DMODEL];
__device__ half  g_qh [NTOK * DMODEL];
__device__ half  g_kh [NTOK * DMODEL];
__device__ half  g_vh [NTOK * DMODEL];
__device__ half  g_oh [NTOK * DMODEL];
__device__ half  g_h2h[NTOK * DMODEL];
__device__ half  g_fh [NTOK * DFFN];
__device__ float g_h  [NTOK * DMODEL];
__device__ float g_t  [NTOK * DMODEL];
__device__ half  g_wqh[DMODEL * DMODEL];
__device__ half  g_wkh[DMODEL * DMODEL];
__device__ half  g_wvh[DMODEL * DMODEL];
__device__ half  g_woh[DMODEL * DMODEL];
__device__ half  g_w1h[DFFN * DMODEL];
__device__ half  g_w2h[DMODEL * DFFN];

// ---------------- helpers ---------------------------------------------------------
__device__ __forceinline__ uint32_t h2_u32(half2 h) {
    return *(uint32_t*)&h;
}

__device__ __forceinline__ void mma16n8k16(float d[4],
                                           uint32_t a0, uint32_t a1, uint32_t a2, uint32_t a3,
                                           uint32_t b0, uint32_t b1) {
    asm volatile("mma.sync.aligned.m16n8k16.row.col.f32.f16.f16.f32 "
                 "{%0,%1,%2,%3}, {%4,%5,%6,%7}, {%8,%9}, {%0,%1,%2,%3};"
                 : "+f"(d[0]), "+f"(d[1]), "+f"(d[2]), "+f"(d[3])
                 : "r"(a0), "r"(a1), "r"(a2), "r"(a3), "r"(b0), "r"(b1));
}

__device__ __forceinline__ void ldmatrix_x4(uint32_t r[4], uint32_t addr) {
    asm volatile("ldmatrix.sync.aligned.m8n8.x4.shared.b16 {%0,%1,%2,%3}, [%4];"
                 : "=r"(r[0]), "=r"(r[1]), "=r"(r[2]), "=r"(r[3]) : "r"(addr));
}

__device__ __forceinline__ void cp_async16(uint32_t saddr, const void* gptr) {
    asm volatile("cp.async.cg.shared.global [%0], [%1], 16;"
                 :: "r"(saddr), "l"(gptr) : "memory");
}
#define CP_COMMIT() asm volatile("cp.async.commit_group;" ::: "memory")
#define CP_WAIT1()  asm volatile("cp.async.wait_group 1;" ::: "memory")
#define CP_WAIT0()  asm volatile("cp.async.wait_group 0;" ::: "memory")

__device__ __forceinline__ void store2(float* p, float a, float b) {
    *(float2*)p = make_float2(a, b);
}
__device__ __forceinline__ void store2(half* p, float a, float b) {
    *(half2*)p = __floats2half2_rn(a, b);
}

// ---------------- merged fp32 -> fp16 convert --------------------------------------
struct CvtArgs {
    const float* in[8];
    half* out[8];
    int n4[8];
};

__global__ void __launch_bounds__(256)
cvt_all(CvtArgs a)
{
    const int s = blockIdx.y;
    const float* in = a.in[s];
    half* out = a.out[s];
    const int n4 = a.n4[s];
    for (int i = blockIdx.x * blockDim.x + threadIdx.x; i < n4;
         i += gridDim.x * blockDim.x) {
        float4 v = ((const float4*)in)[i];
        ((half2*)out)[2 * i + 0] = __floats2half2_rn(v.x, v.y);
        ((half2*)out)[2 * i + 1] = __floats2half2_rn(v.z, v.w);
    }
}

// ---------------- mma.sync fp16 GEMM, 3-stage cp.async pipeline --------------------
// C[M,N] = A[M,K] @ W[N,K]^T + bias (+ epilogue). kind: 0=bias, 1=+res, 2=+GELU.
// CTA 64x128, 8 warps (2x4), warp tile 32x32 -> 32 accum regs, 3 CTAs/SM.
// K-chunks of 32, 3 smem stages, prefetch issued after the MMA block.
#define PADH2     20
#define A_TILE_H2 (64 * PADH2)       // 1280 half2
#define B_TILE_H2 (128 * PADH2)      // 2560 half2
#define A_TILE_BY (A_TILE_H2 * 4)    // 5120 B
#define STAGE_H2  (A_TILE_H2 + B_TILE_H2)
#define STAGE_BY  (STAGE_H2 * 4)     // 15360 B
#define SMEM_BY   (3 * STAGE_BY)     // 46080 B

template<typename OutT>
__device__ __forceinline__ void gemm_body(
    const half* __restrict__ A, const half* __restrict__ W,
    const float* __restrict__ bias, const float* __restrict__ res,
    OutT* __restrict__ C, int N, int K, int kind)
{
    extern __shared__ uint32_t smem[];

    const int tid  = threadIdx.x;
    const int wid  = tid >> 5;
    const int lane = tid & 31;
    const int g    = lane >> 2;
    const int tig  = lane & 3;
    const int bm   = blockIdx.y * 64, bn = blockIdx.x * 128;
    const int wm   = (wid >> 2) * 32;   // warp m offset (0/32)
    const int wn   = (wid & 3) * 32;    // warp n offset (0/32/64/96)

    const uint32_t sbase = (uint32_t)__cvta_generic_to_shared(smem);

    const int mat = lane >> 3, rin = lane & 7;
    const uint32_t a_lane = sbase +
        4u * ((wm + (mat & 1) * 8 + rin) * PADH2 + (mat >> 1) * 4);
    const uint32_t b_lane = sbase + A_TILE_BY +
        4u * ((wn + (mat >> 1) * 8 + rin) * PADH2 + (mat & 1) * 4);

    float d[2][4][4];
#pragma unroll
    for (int mi = 0; mi < 2; mi++)
#pragma unroll
        for (int ni = 0; ni < 4; ni++)
#pragma unroll
            for (int e = 0; e < 4; e++) d[mi][ni][e] = 0.f;

    // global load mapping:
    //   A: 4 threads/row, 8 halfs (16B) each  -> 1 cp.async
    //   B: 2 threads/row, 16 halfs (32B) each -> 2 cp.async
    const int ar = tid >> 2, ac = (tid & 3) * 8;
    const int br = tid >> 1, bc = (tid & 1) * 16;
    const half* aptr = &A[(size_t)(bm + ar) * K + ac];
    const half* bptr = &W[(size_t)(bn + br) * K + bc];
    const uint32_t a_soff = 4u * (ar * PADH2 + (ac >> 1));
    const uint32_t b_soff = (uint32_t)A_TILE_BY + 4u * (br * PADH2 + (bc >> 1));

    const int NC = K >> 5;

    auto issue = [&](int stage, int c) {
        const half* ap = aptr + (c << 5);
        const half* bp = bptr + (c << 5);
        uint32_t sa = sbase + stage * STAGE_BY + a_soff;
        uint32_t sb = sbase + stage * STAGE_BY + b_soff;
        cp_async16(sa,      ap);
        cp_async16(sb,      bp);
        cp_async16(sb + 16, bp + 8);
        CP_COMMIT();
    };

    // prologue: 2 stages in flight
    issue(0, 0);
    issue(1, 1);

    int stage = 0;
    for (int c = 0; c < NC; c++) {
        CP_WAIT1();
        __syncthreads();

        const uint32_t abase = a_lane + stage * STAGE_BY;
        const uint32_t bbase = b_lane + stage * STAGE_BY;

#pragma unroll
        for (int ks = 0; ks < 2; ks++) {
            const uint32_t koff = 4u * (ks * 8);
            uint32_t afr[2][4], bfr[2][4];
#pragma unroll
            for (int mi = 0; mi < 2; mi++)
                ldmatrix_x4(afr[mi], abase + koff + 4u * (mi * 16 * PADH2));
#pragma unroll
            for (int j = 0; j < 2; j++)
                ldmatrix_x4(bfr[j], bbase + koff + 4u * (j * 16 * PADH2));
#pragma unroll
            for (int mi = 0; mi < 2; mi++)
#pragma unroll
                for (int ni = 0; ni < 4; ni++)
                    mma16n8k16(d[mi][ni],
                               afr[mi][0], afr[mi][1], afr[mi][2], afr[mi][3],
                               bfr[ni >> 1][(ni & 1) * 2], bfr[ni >> 1][(ni & 1) * 2 + 1]);
        }

        if (c + 2 < NC) {
            int nst = stage + 2; if (nst >= 3) nst -= 3;
            issue(nst, c + 2);
        }
        stage = (stage + 1 == 3) ? 0 : stage + 1;
    }

    // epilogue
#pragma unroll
    for (int mi = 0; mi < 2; mi++) {
#pragma unroll
        for (int rh = 0; rh < 2; rh++) {
            const int m = bm + wm + mi * 16 + g + rh * 8;
            OutT* crow = &C[(size_t)m * N];
            const float* rrow = res ? &res[(size_t)m * N] : nullptr;
#pragma unroll
            for (int ni = 0; ni < 4; ni++) {
                const int n = bn + wn + ni * 8 + 2 * tig;
                float v0 = d[mi][ni][rh * 2 + 0] + bias[n];
                float v1 = d[mi][ni][rh * 2 + 1] + bias[n + 1];
                if (kind == 1) {
                    v0 += rrow[n]; v1 += rrow[n + 1];
                } else if (kind == 2) {
                    v0 = 0.5f * v0 * (1.0f + erff(v0 * 0.70710678118654752f));
                    v1 = 0.5f * v1 * (1.0f + erff(v1 * 0.70710678118654752f));
                }
                store2(&crow[n], v0, v1);
            }
        }
    }
}

// merged Q/K/V projection: blockIdx.z selects the problem
__global__ void __launch_bounds__(256, 3)
qkv_gemm(const half* __restrict__ xh, const half* __restrict__ x1h,
         const half* __restrict__ wq, const half* __restrict__ wk,
         const half* __restrict__ wv,
         const float* __restrict__ bq, const float* __restrict__ bk,
         const float* __restrict__ bv,
         half* __restrict__ q, half* __restrict__ k, half* __restrict__ v)
{
    const half* A; const half* W; const float* B; half* C;
    if (blockIdx.z == 0)      { A = xh;  W = wq; B = bq; C = q; }
    else if (blockIdx.z == 1) { A = x1h; W = wk; B = bk; C = k; }
    else                      { A = x1h; W = wv; B = bv; C = v; }
    gemm_body<half>(A, W, B, nullptr, C, DMODEL, DMODEL, 0);
}

template<typename OutT>
__global__ void __launch_bounds__(256, 3)
gemm_h(const half* __restrict__ A, const half* __restrict__ W,
       const float* __restrict__ bias, const float* __restrict__ res,
       OutT* __restrict__ C, int N, int K, int kind)
{
    gemm_body<OutT>(A, W, bias, res, C, N, K, kind);
}

// ---------------- Tensor-core flash attention (fp16 in/out) ------------------------
// Pipelined K/V: sk double-buffered via cp.async; V prefetched into registers one
// iteration ahead, scattered with XOR swizzle:
//   sv_idx(d, r) = d*QPAD + (r&7) + 8*((r>>3) ^ ((d>>3)&7))
#define QPAD 72
#define SK_BY (64 * QPAD * 2)   // bytes per K buffer

__global__ void __launch_bounds__(256)
attn_mma(const half* __restrict__ Qp, const half* __restrict__ Kp,
         const half* __restrict__ Vp, half* __restrict__ Op)
{
    __shared__ __align__(16) half sq[128 * QPAD];
    __shared__ __align__(16) half sk[2][64 * QPAD];
    __shared__ __align__(16) half sv[64 * QPAD];

    const int tid  = threadIdx.x;
    const int wq   = tid >> 5;
    const int lane = tid & 31;
    const int g    = lane >> 2;
    const int tig  = lane & 3;
    const int qb = blockIdx.x, h = blockIdx.y, b = blockIdx.z;
    const int base_q = b * SEQ + qb * 128;
    const int hoff   = h * DHD;

    const uint32_t sk_u32 = (uint32_t)__cvta_generic_to_shared(&sk[0][0]);

    // K/V loader mapping: 4 threads per row, 16 halfs each
    const int kvr = tid >> 2, kvc = (tid & 3) * 16;

    auto k_issue = [&](int kb) {
        const half* kp = &Kp[(size_t)(b * SEQ + kb * 64 + kvr) * DMODEL + hoff + kvc];
        uint32_t dst = sk_u32 + (kb & 1) * SK_BY + 2u * (kvr * QPAD + kvc);
        cp_async16(dst,      kp);
        cp_async16(dst + 16, kp + 8);
        CP_COMMIT();
    };
    uint4 vreg[2];
    auto v_load = [&](int kb) {
        const uint4* vp = (const uint4*)&Vp[(size_t)(b * SEQ + kb * 64 + kvr) * DMODEL + hoff + kvc];
        vreg[0] = vp[0]; vreg[1] = vp[1];
    };

    // prologue
    k_issue(0);
    v_load(0);
    {
        const int r = tid >> 1, c0 = (tid & 1) * 32;
        const uint4* qp = (const uint4*)&Qp[(size_t)(base_q + r) * DMODEL + hoff + c0];
        uint4* dst = (uint4*)&sq[r * QPAD + c0];
        dst[0] = qp[0]; dst[1] = qp[1]; dst[2] = qp[2]; dst[3] = qp[3];
    }
    __syncthreads();

    uint32_t qf[4][4];
#pragma unroll
    for (int ks = 0; ks < 4; ks++) {
        const half* p = &sq[(wq * 16 + g) * QPAD + ks * 16 + 2 * tig];
        qf[ks][0] = *(const uint32_t*)p;
        qf[ks][1] = *(const uint32_t*)(p + 8 * QPAD);
        qf[ks][2] = *(const uint32_t*)(p + 8);
        qf[ks][3] = *(const uint32_t*)(p + 8 * QPAD + 8);
    }

    float oa[8][4];
#pragma unroll
    for (int no = 0; no < 8; no++)
#pragma unroll
        for (int e = 0; e < 4; e++) oa[no][e] = 0.f;
    float m0 = -1e30f, m1 = -1e30f, l0 = 0.f, l1 = 0.f;

    const float SC  = 0.125f;
    const float L2E = 1.4426950408889634f;

    for (int kb = 0; kb < SEQ / 64; kb++) {
        CP_WAIT0();
        __syncthreads();

        {
            half tmp[16];
            *(uint4*)&tmp[0] = vreg[0];
            *(uint4*)&tmp[8] = vreg[1];
            const int rlo = kvr & 7, rhi = kvr >> 3;
#pragma unroll
            for (int j = 0; j < 16; j++) {
                const int d = kvc + j;
                sv[d * QPAD + rlo + 8 * (rhi ^ ((d >> 3) & 7))] = tmp[j];
            }
        }
        if (kb + 1 < SEQ / 64) {
            k_issue(kb + 1);
            v_load(kb + 1);
        }
        __syncthreads();

        const half* skb = &sk[kb & 1][0];

        float sf[8][4];
#pragma unroll
        for (int ni = 0; ni < 8; ni++) {
            sf[ni][0] = sf[ni][1] = sf[ni][2] = sf[ni][3] = 0.f;
            const half* kr = &skb[(ni * 8 + g) * QPAD + 2 * tig];
#pragma unroll
            for (int ks = 0; ks < 4; ks++) {
                uint32_t b0 = *(const uint32_t*)(kr + ks * 16);
                uint32_t b1 = *(const uint32_t*)(kr + ks * 16 + 8);
                mma16n8k16(sf[ni], qf[ks][0], qf[ks][1], qf[ks][2], qf[ks][3], b0, b1);
            }
        }

        float mx0 = -1e30f, mx1 = -1e30f;
#pragma unroll
        for (int ni = 0; ni < 8; ni++) {
            mx0 = fmaxf(mx0, fmaxf(sf[ni][0], sf[ni][1]));
            mx1 = fmaxf(mx1, fmaxf(sf[ni][2], sf[ni][3]));
        }
        mx0 *= SC; mx1 *= SC;
        mx0 = fmaxf(mx0, __shfl_xor_sync(~0u, mx0, 1));
        mx0 = fmaxf(mx0, __shfl_xor_sync(~0u, mx0, 2));
        mx1 = fmaxf(mx1, __shfl_xor_sync(~0u, mx1, 1));
        mx1 = fmaxf(mx1, __shfl_xor_sync(~0u, mx1, 2));

        const float mn0 = fmaxf(m0, mx0), mn1 = fmaxf(m1, mx1);
        const float c0f = __expf(m0 - mn0), c1f = __expf(m1 - mn1);
        m0 = mn0; m1 = mn1;
        l0 *= c0f; l1 *= c1f;
#pragma unroll
        for (int no = 0; no < 8; no++) {
            oa[no][0] *= c0f; oa[no][1] *= c0f;
            oa[no][2] *= c1f; oa[no][3] *= c1f;
        }

        uint32_t af[4][4];
        float sum0 = 0.f, sum1 = 0.f;
#pragma unroll
        for (int ni = 0; ni < 8; ni++) {
            half2 p0 = h2exp2(__floats2half2_rn((sf[ni][0] * SC - m0) * L2E,
                                                (sf[ni][1] * SC - m0) * L2E));
            half2 p1 = h2exp2(__floats2half2_rn((sf[ni][2] * SC - m1) * L2E,
                                                (sf[ni][3] * SC - m1) * L2E));
            float2 f0 = __half22float2(p0); sum0 += f0.x + f0.y;
            float2 f1 = __half22float2(p1); sum1 += f1.x + f1.y;
            const int ki = ni >> 1;
            if ((ni & 1) == 0) { af[ki][0] = h2_u32(p0); af[ki][1] = h2_u32(p1); }
            else               { af[ki][2] = h2_u32(p0); af[ki][3] = h2_u32(p1); }
        }
        l0 += sum0; l1 += sum1;

#pragma unroll
        for (int ki = 0; ki < 4; ki++) {
#pragma unroll
            for (int no = 0; no < 8; no++) {
                const half* vr = &sv[(no * 8 + g) * QPAD + 2 * tig];
                uint32_t b0 = *(const uint32_t*)(vr + 8 * ((2 * ki) ^ no));
                uint32_t b1 = *(const uint32_t*)(vr + 8 * ((2 * ki + 1) ^ no));
                mma16n8k16(oa[no], af[ki][0], af[ki][1], af[ki][2], af[ki][3], b0, b1);
            }
        }
    }

    l0 += __shfl_xor_sync(~0u, l0, 1); l0 += __shfl_xor_sync(~0u, l0, 2);
    l1 += __shfl_xor_sync(~0u, l1, 1); l1 += __shfl_xor_sync(~0u, l1, 2);
    const float inv0 = 1.f / l0, inv1 = 1.f / l1;

    const int row0 = base_q + wq * 16 + g;
#pragma unroll
    for (int no = 0; no < 8; no++) {
        const int n = hoff + no * 8 + 2 * tig;
        store2(&Op[(size_t)row0 * DMODEL + n], oa[no][0] * inv0, oa[no][1] * inv0);
        store2(&Op[(size_t)(row0 + 8) * DMODEL + n], oa[no][2] * inv1, oa[no][3] * inv1);
    }
}

// ---------------- LayerNorm: one row per CTA, 256 threads -----------------------
template<typename OutT>
__global__ void __launch_bounds__(256)
ln_kernel(const float* __restrict__ X, const float* __restrict__ gam,
          const float* __restrict__ bet, OutT* __restrict__ Y)
{
    const int row = blockIdx.x;
    const int t   = threadIdx.x;
    const int lane = t & 31, wid = t >> 5;
    const float* x = X + (size_t)row * DMODEL;

    float v0 = x[t], v1 = x[t + 256], v2 = x[t + 512];
    float s = v0 + v1 + v2;

    __shared__ float sbuf[8];
    __shared__ float s_mu, s_rstd;

#pragma unroll
    for (int o = 16; o > 0; o >>= 1) s += __shfl_xor_sync(~0u, s, o);
    if (lane == 0) sbuf[wid] = s;
    __syncthreads();
    if (t == 0) {
        float tot = 0.f;
        for (int i = 0; i < 8; i++) tot += sbuf[i];
        s_mu = tot * (1.0f / DMODEL);
    }
    __syncthreads();
    const float mu = s_mu;

    float d0 = v0 - mu, d1 = v1 - mu, d2 = v2 - mu;
    float qv = d0 * d0 + d1 * d1 + d2 * d2;
#pragma unroll
    for (int o = 16; o > 0; o >>= 1) qv += __shfl_xor_sync(~0u, qv, o);
    if (lane == 0) sbuf[wid] = qv;
    __syncthreads();
    if (t == 0) {
        float tot = 0.f;
        for (int i = 0; i < 8; i++) tot += sbuf[i];
        s_rstd = rsqrtf(tot * (1.0f / DMODEL) + LN_EPS);
    }
    __syncthreads();
    const float rstd = s_rstd;

    Y[(size_t)row * DMODEL + t      ] = (OutT)(d0 * rstd * gam[t      ] + bet[t      ]);
    Y[(size_t)row * DMODEL + t + 256] = (OutT)(d1 * rstd * gam[t + 256] + bet[t + 256]);
    Y[(size_t)row * DMODEL + t + 512] = (OutT)(d2 * rstd * gam[t + 512] + bet[t + 512]);
}

// ---------------- launch --------------------------------------------------------
extern "C" void kernel_launch(void* const* d_in, const int* in_sizes, int n_in,
                              void* d_out, int out_size)
{
    const float* x    = (const float*)d_in[0];
    const float* x1   = (const float*)d_in[1];
    const float* Wq   = (const float*)d_in[2];
    const float* bq   = (const float*)d_in[3];
    const float* Wk   = (const float*)d_in[4];
    const float* bk   = (const float*)d_in[5];
    const float* Wv   = (const float*)d_in[6];
    const float* bv   = (const float*)d_in[7];
    const float* Wo   = (const float*)d_in[8];
    const float* bo   = (const float*)d_in[9];
    const float* W1   = (const float*)d_in[10];
    const float* b1   = (const float*)d_in[11];
    const float* W2   = (const float*)d_in[12];
    const float* b2   = (const float*)d_in[13];
    const float* ln1g = (const float*)d_in[14];
    const float* ln1b = (const float*)d_in[15];
    const float* ln2g = (const float*)d_in[16];
    const float* ln2b = (const float*)d_in[17];
    float* out = (float*)d_out;

    half *xh, *x1h, *qh, *kh, *vh, *oh, *h2h, *fh;
    half *wqh, *wkh, *wvh, *woh, *w1h, *w2h;
    float *h, *tbuf;
    cudaGetSymbolAddress((void**)&xh,  g_xh);
    cudaGetSymbolAddress((void**)&x1h, g_x1h);
    cudaGetSymbolAddress((void**)&qh,  g_qh);
    cudaGetSymbolAddress((void**)&kh,  g_kh);
    cudaGetSymbolAddress((void**)&vh,  g_vh);
    cudaGetSymbolAddress((void**)&oh,  g_oh);
    cudaGetSymbolAddress((void**)&h2h, g_h2h);
    cudaGetSymbolAddress((void**)&fh,  g_fh);
    cudaGetSymbolAddress((void**)&h,   g_h);
    cudaGetSymbolAddress((void**)&tbuf,g_t);
    cudaGetSymbolAddress((void**)&wqh, g_wqh);
    cudaGetSymbolAddress((void**)&wkh, g_wkh);
    cudaGetSymbolAddress((void**)&wvh, g_wvh);
    cudaGetSymbolAddress((void**)&woh, g_woh);
    cudaGetSymbolAddress((void**)&w1h, g_w1h);
    cudaGetSymbolAddress((void**)&w2h, g_w2h);

    cudaFuncSetAttribute(qkv_gemm, cudaFuncAttributeMaxDynamicSharedMemorySize, SMEM_BY);
    cudaFuncSetAttribute(gemm_h<float>, cudaFuncAttributeMaxDynamicSharedMemorySize, SMEM_BY);
    cudaFuncSetAttribute(gemm_h<half>,  cudaFuncAttributeMaxDynamicSharedMemorySize, SMEM_BY);

    // merged one-time fp32 -> fp16 converts
    {
        CvtArgs ca;
        ca.in[0] = x;  ca.out[0] = xh;  ca.n4[0] = NTOK * DMODEL / 4;
        ca.in[1] = x1; ca.out[1] = x1h; ca.n4[1] = NTOK * DMODEL / 4;
        ca.in[2] = Wq; ca.out[2] = wqh; ca.n4[2] = DMODEL * DMODEL / 4;
        ca.in[3] = Wk; ca.out[3] = wkh; ca.n4[3] = DMODEL * DMODEL / 4;
        ca.in[4] = Wv; ca.out[4] = wvh; ca.n4[4] = DMODEL * DMODEL / 4;
        ca.in[5] = Wo; ca.out[5] = woh; ca.n4[5] = DMODEL * DMODEL / 4;
        ca.in[6] = W1; ca.out[6] = w1h; ca.n4[6] = DFFN * DMODEL / 4;
        ca.in[7] = W2; ca.out[7] = w2h; ca.n4[7] = DMODEL * DFFN / 4;
        cvt_all<<<dim3(128, 8), 256>>>(ca);
    }

    dim3 blk(256);

    // merged Q/K/V projections (CTA tile 64x128)
    qkv_gemm<<<dim3(DMODEL / 128, NTOK / 64, 3), blk, SMEM_BY>>>(
        xh, x1h, wqh, wkh, wvh, bq, bk, bv, qh, kh, vh);

    attn_mma<<<dim3(SEQ / 128, NH, NBATCH), 256>>>(qh, kh, vh, oh);

    // output projection + residual -> h (fp32)
    gemm_h<float><<<dim3(DMODEL / 128, NTOK / 64), blk, SMEM_BY>>>(
        oh, woh, bo, x, h, DMODEL, DMODEL, 1);

    // h2 = LN(h, ln2) -> fp16
    ln_kernel<half><<<NTOK, 256>>>(h, ln2g, ln2b, h2h);

    // FFN1: GELU -> fp16
    gemm_h<half><<<dim3(DFFN / 128, NTOK / 64), blk, SMEM_BY>>>(
        h2h, w1h, b1, nullptr, fh, DFFN, DMODEL, 2);

    // FFN2: + residual h -> fp32
    gemm_h<float><<<dim3(DMODEL / 128, NTOK / 64), blk, SMEM_BY>>>(
        fh, w2h, b2, h, tbuf, DMODEL, DFFN, 1);

    // out = LN(h + ffn, ln1) -> fp32
    ln_kernel<float><<<NTOK, 256>>>(tbuf, ln1g, ln1b, out);
}

// round 17
// speedup vs baseline: 1.0876x; 1.0876x over previous
#include <cuda_runtime.h>
#include <cuda_fp16.h>
#include <math.h>
#include <stdint.h>

#define NTOK   8192
#define DMODEL 768
#define DFFN   3072
#define NH     12
#define DHD    64
#define SEQ    1024
#define NBATCH 8
#define LN_EPS 1e-6f

// ---------------- scratch (static device globals; no allocation) ----------------
__device__ half  g_xh [NTOK * DMODEL];
__device__ half  g_x1h[NTOK * DMODEL];
__device__ half  g_qh [NTOK * DMODEL];
__device__ half  g_kh [NTOK * DMODEL];
__device__ half  g_vh [NTOK * DMODEL];
__device__ half  g_oh [NTOK * DMODEL];
__device__ half  g_h2h[NTOK * DMODEL];
__device__ half  g_fh [NTOK * DFFN];
__device__ float g_h  [NTOK * DMODEL];
__device__ float g_t  [NTOK * DMODEL];
__device__ half  g_wqh[DMODEL * DMODEL];
__device__ half  g_wkh[DMODEL * DMODEL];
__device__ half  g_wvh[DMODEL * DMODEL];
__device__ half  g_woh[DMODEL * DMODEL];
__device__ half  g_w1h[DFFN * DMODEL];
__device__ half  g_w2h[DMODEL * DFFN];

// ---------------- helpers ---------------------------------------------------------
__device__ __forceinline__ uint32_t h2_u32(half2 h) {
    return *(uint32_t*)&h;
}

__device__ __forceinline__ void mma16n8k16(float d[4],
                                           uint32_t a0, uint32_t a1, uint32_t a2, uint32_t a3,
                                           uint32_t b0, uint32_t b1) {
    asm volatile("mma.sync.aligned.m16n8k16.row.col.f32.f16.f16.f32 "
                 "{%0,%1,%2,%3}, {%4,%5,%6,%7}, {%8,%9}, {%0,%1,%2,%3};"
                 : "+f"(d[0]), "+f"(d[1]), "+f"(d[2]), "+f"(d[3])
                 : "r"(a0), "r"(a1), "r"(a2), "r"(a3), "r"(b0), "r"(b1));
}

__device__ __forceinline__ void ldmatrix_x4(uint32_t r[4], uint32_t addr) {
    asm volatile("ldmatrix.sync.aligned.m8n8.x4.shared.b16 {%0,%1,%2,%3}, [%4];"
                 : "=r"(r[0]), "=r"(r[1]), "=r"(r[2]), "=r"(r[3]) : "r"(addr));
}

__device__ __forceinline__ void cp_async16(uint32_t saddr, const void* gptr) {
    asm volatile("cp.async.cg.shared.global [%0], [%1], 16;"
                 :: "r"(saddr), "l"(gptr) : "memory");
}
#define CP_COMMIT() asm volatile("cp.async.commit_group;" ::: "memory")
#define CP_WAIT2()  asm volatile("cp.async.wait_group 2;" ::: "memory")
#define CP_WAIT0()  asm volatile("cp.async.wait_group 0;" ::: "memory")

__device__ __forceinline__ void store2(float* p, float a, float b) {
    *(float2*)p = make_float2(a, b);
}
__device__ __forceinline__ void store2(half* p, float a, float b) {
    *(half2*)p = __floats2half2_rn(a, b);
}

// ---------------- merged fp32 -> fp16 convert --------------------------------------
struct CvtArgs {
    const float* in[8];
    half* out[8];
    int n4[8];
};

__global__ void __launch_bounds__(256)
cvt_all(CvtArgs a)
{
    const int s = blockIdx.y;
    const float* in = a.in[s];
    half* out = a.out[s];
    const int n4 = a.n4[s];
    for (int i = blockIdx.x * blockDim.x + threadIdx.x; i < n4;
         i += gridDim.x * blockDim.x) {
        float4 v = ((const float4*)in)[i];
        ((half2*)out)[2 * i + 0] = __floats2half2_rn(v.x, v.y);
        ((half2*)out)[2 * i + 1] = __floats2half2_rn(v.z, v.w);
    }
}

// ---------------- mma.sync fp16 GEMM, 4-stage cp.async pipeline --------------------
// C[M,N] = A[M,K] @ W[N,K]^T + bias (+ epilogue). kind: 0=bias, 1=+res, 2=+GELU.
// CTA 128x128, 8 warps (2x4), warp tile 64x32. K-chunks of 32, 4 smem stages,
// prefetch distance 3, issue AFTER the MMA block.
#define PADH2    20
#define TILE_H2  (128 * PADH2)
#define TILE_BY  (TILE_H2 * 4)      // bytes per operand tile (10240)
#define STAGE_BY (2 * TILE_BY)      // bytes per stage (A + B) = 20480
#define NSTAGE   4
#define SMEM_BY  (NSTAGE * STAGE_BY) // 81920

template<typename OutT>
__device__ __forceinline__ void gemm_body(
    const half* __restrict__ A, const half* __restrict__ W,
    const float* __restrict__ bias, const float* __restrict__ res,
    OutT* __restrict__ C, int N, int K, int kind)
{
    extern __shared__ uint32_t smem[];

    const int tid  = threadIdx.x;
    const int wid  = tid >> 5;
    const int lane = tid & 31;
    const int g    = lane >> 2;
    const int tig  = lane & 3;
    const int bm   = blockIdx.y * 128, bn = blockIdx.x * 128;
    const int wm   = (wid >> 2) * 64;
    const int wn   = (wid & 3) * 32;

    const uint32_t sbase = (uint32_t)__cvta_generic_to_shared(smem);

    const int mat = lane >> 3, rin = lane & 7;
    const uint32_t a_lane = sbase +
        4u * ((wm + (mat & 1) * 8 + rin) * PADH2 + (mat >> 1) * 4);
    const uint32_t b_lane = sbase + TILE_BY +
        4u * ((wn + (mat >> 1) * 8 + rin) * PADH2 + (mat & 1) * 4);

    float d[4][4][4];
#pragma unroll
    for (int mi = 0; mi < 4; mi++)
#pragma unroll
        for (int ni = 0; ni < 4; ni++)
#pragma unroll
            for (int e = 0; e < 4; e++) d[mi][ni][e] = 0.f;

    // global load mapping: 2 threads per row, 16 halfs (32B) each
    const int grow = tid >> 1;
    const half* aptr = &A[(size_t)(bm + grow) * K + (tid & 1) * 16];
    const half* bptr = &W[(size_t)(bn + grow) * K + (tid & 1) * 16];
    const uint32_t s_off = 4u * (grow * PADH2 + (tid & 1) * 8);

    const int NC = K >> 5;

    auto issue = [&](int stage, int c) {
        const half* ap = aptr + (c << 5);
        const half* bp = bptr + (c << 5);
        uint32_t sa = sbase + stage * STAGE_BY + s_off;
        uint32_t sb = sa + TILE_BY;
        cp_async16(sa,      ap);
        cp_async16(sa + 16, ap + 8);
        cp_async16(sb,      bp);
        cp_async16(sb + 16, bp + 8);
        CP_COMMIT();
    };

    // prologue: 3 stages in flight (K >= 128 always => NC >= 4)
    issue(0, 0);
    issue(1, 1);
    issue(2, 2);

    int stage = 0;
    for (int c = 0; c < NC; c++) {
        CP_WAIT2();           // chunk c's group complete (<=2 younger pending)
        __syncthreads();      // all warps see it; all done reading stage of c-1

        const uint32_t abase = a_lane + stage * STAGE_BY;
        const uint32_t bbase = b_lane + stage * STAGE_BY;

#pragma unroll
        for (int ks = 0; ks < 2; ks++) {
            const uint32_t koff = 4u * (ks * 8);
            uint32_t afr[4][4], bfr[2][4];
#pragma unroll
            for (int mi = 0; mi < 4; mi++)
                ldmatrix_x4(afr[mi], abase + koff + 4u * (mi * 16 * PADH2));
#pragma unroll
            for (int j = 0; j < 2; j++)
                ldmatrix_x4(bfr[j], bbase + koff + 4u * (j * 16 * PADH2));
#pragma unroll
            for (int mi = 0; mi < 4; mi++)
#pragma unroll
                for (int ni = 0; ni < 4; ni++)
                    mma16n8k16(d[mi][ni],
                               afr[mi][0], afr[mi][1], afr[mi][2], afr[mi][3],
                               bfr[ni >> 1][(ni & 1) * 2], bfr[ni >> 1][(ni & 1) * 2 + 1]);
        }

        // issue chunk c+3 into stage (c-1)%4 — drained per the barrier above
        if (c + 3 < NC) {
            int nst = stage + 3; if (nst >= NSTAGE) nst -= NSTAGE;
            issue(nst, c + 3);
        }
        stage = (stage + 1 == NSTAGE) ? 0 : stage + 1;
    }

    // epilogue: fragment (mi,ni): rows wm+mi*16+g / +8, cols wn+ni*8+2*tig / +1
#pragma unroll
    for (int mi = 0; mi < 4; mi++) {
#pragma unroll
        for (int rh = 0; rh < 2; rh++) {
            const int m = bm + wm + mi * 16 + g + rh * 8;
            OutT* crow = &C[(size_t)m * N];
            const float* rrow = res ? &res[(size_t)m * N] : nullptr;
#pragma unroll
            for (int ni = 0; ni < 4; ni++) {
                const int n = bn + wn + ni * 8 + 2 * tig;
                float v0 = d[mi][ni][rh * 2 + 0] + bias[n];
                float v1 = d[mi][ni][rh * 2 + 1] + bias[n + 1];
                if (kind == 1) {
                    v0 += rrow[n]; v1 += rrow[n + 1];
                } else if (kind == 2) {
                    v0 = 0.5f * v0 * (1.0f + erff(v0 * 0.70710678118654752f));
                    v1 = 0.5f * v1 * (1.0f + erff(v1 * 0.70710678118654752f));
                }
                store2(&crow[n], v0, v1);
            }
        }
    }
}

// merged Q/K/V projection: blockIdx.z selects the problem
__global__ void __launch_bounds__(256)
qkv_gemm(const half* __restrict__ xh, const half* __restrict__ x1h,
         const half* __restrict__ wq, const half* __restrict__ wk,
         const half* __restrict__ wv,
         const float* __restrict__ bq, const float* __restrict__ bk,
         const float* __restrict__ bv,
         half* __restrict__ q, half* __restrict__ k, half* __restrict__ v)
{
    const half* A; const half* W; const float* B; half* C;
    if (blockIdx.z == 0)      { A = xh;  W = wq; B = bq; C = q; }
    else if (blockIdx.z == 1) { A = x1h; W = wk; B = bk; C = k; }
    else                      { A = x1h; W = wv; B = bv; C = v; }
    gemm_body<half>(A, W, B, nullptr, C, DMODEL, DMODEL, 0);
}

template<typename OutT>
__global__ void __launch_bounds__(256)
gemm_h(const half* __restrict__ A, const half* __restrict__ W,
       const float* __restrict__ bias, const float* __restrict__ res,
       OutT* __restrict__ C, int N, int K, int kind)
{
    gemm_body<OutT>(A, W, bias, res, C, N, K, kind);
}

// ---------------- Tensor-core flash attention (fp16 in/out) ------------------------
// Pipelined K/V: sk double-buffered via cp.async; V prefetched into registers one
// iteration ahead, scattered with XOR swizzle:
//   sv_idx(d, r) = d*QPAD + (r&7) + 8*((r>>3) ^ ((d>>3)&7))
#define QPAD 72
#define SK_BY (64 * QPAD * 2)   // bytes per K buffer

__global__ void __launch_bounds__(256)
attn_mma(const half* __restrict__ Qp, const half* __restrict__ Kp,
         const half* __restrict__ Vp, half* __restrict__ Op)
{
    __shared__ __align__(16) half sq[128 * QPAD];
    __shared__ __align__(16) half sk[2][64 * QPAD];
    __shared__ __align__(16) half sv[64 * QPAD];

    const int tid  = threadIdx.x;
    const int wq   = tid >> 5;
    const int lane = tid & 31;
    const int g    = lane >> 2;
    const int tig  = lane & 3;
    const int qb = blockIdx.x, h = blockIdx.y, b = blockIdx.z;
    const int base_q = b * SEQ + qb * 128;
    const int hoff   = h * DHD;

    const uint32_t sk_u32 = (uint32_t)__cvta_generic_to_shared(&sk[0][0]);

    // K/V loader mapping: 4 threads per row, 16 halfs each
    const int kvr = tid >> 2, kvc = (tid & 3) * 16;

    auto k_issue = [&](int kb) {
        const half* kp = &Kp[(size_t)(b * SEQ + kb * 64 + kvr) * DMODEL + hoff + kvc];
        uint32_t dst = sk_u32 + (kb & 1) * SK_BY + 2u * (kvr * QPAD + kvc);
        cp_async16(dst,      kp);
        cp_async16(dst + 16, kp + 8);
        CP_COMMIT();
    };
    uint4 vreg[2];
    auto v_load = [&](int kb) {
        const uint4* vp = (const uint4*)&Vp[(size_t)(b * SEQ + kb * 64 + kvr) * DMODEL + hoff + kvc];
        vreg[0] = vp[0]; vreg[1] = vp[1];
    };

    // prologue
    k_issue(0);
    v_load(0);
    {
        const int r = tid >> 1, c0 = (tid & 1) * 32;
        const uint4* qp = (const uint4*)&Qp[(size_t)(base_q + r) * DMODEL + hoff + c0];
        uint4* dst = (uint4*)&sq[r * QPAD + c0];
        dst[0] = qp[0]; dst[1] = qp[1]; dst[2] = qp[2]; dst[3] = qp[3];
    }
    __syncthreads();

    uint32_t qf[4][4];
#pragma unroll
    for (int ks = 0; ks < 4; ks++) {
        const half* p = &sq[(wq * 16 + g) * QPAD + ks * 16 + 2 * tig];
        qf[ks][0] = *(const uint32_t*)p;
        qf[ks][1] = *(const uint32_t*)(p + 8 * QPAD);
        qf[ks][2] = *(const uint32_t*)(p + 8);
        qf[ks][3] = *(const uint32_t*)(p + 8 * QPAD + 8);
    }

    float oa[8][4];
#pragma unroll
    for (int no = 0; no < 8; no++)
#pragma unroll
        for (int e = 0; e < 4; e++) oa[no][e] = 0.f;
    float m0 = -1e30f, m1 = -1e30f, l0 = 0.f, l1 = 0.f;

    const float SC  = 0.125f;
    const float L2E = 1.4426950408889634f;

    for (int kb = 0; kb < SEQ / 64; kb++) {
        CP_WAIT0();
        __syncthreads();

        {
            half tmp[16];
            *(uint4*)&tmp[0] = vreg[0];
            *(uint4*)&tmp[8] = vreg[1];
            const int rlo = kvr & 7, rhi = kvr >> 3;
#pragma unroll
            for (int j = 0; j < 16; j++) {
                const int d = kvc + j;
                sv[d * QPAD + rlo + 8 * (rhi ^ ((d >> 3) & 7))] = tmp[j];
            }
        }
        if (kb + 1 < SEQ / 64) {
            k_issue(kb + 1);
            v_load(kb + 1);
        }
        __syncthreads();

        const half* skb = &sk[kb & 1][0];

        float sf[8][4];
#pragma unroll
        for (int ni = 0; ni < 8; ni++) {
            sf[ni][0] = sf[ni][1] = sf[ni][2] = sf[ni][3] = 0.f;
            const half* kr = &skb[(ni * 8 + g) * QPAD + 2 * tig];
#pragma unroll
            for (int ks = 0; ks < 4; ks++) {
                uint32_t b0 = *(const uint32_t*)(kr + ks * 16);
                uint32_t b1 = *(const uint32_t*)(kr + ks * 16 + 8);
                mma16n8k16(sf[ni], qf[ks][0], qf[ks][1], qf[ks][2], qf[ks][3], b0, b1);
            }
        }

        float mx0 = -1e30f, mx1 = -1e30f;
#pragma unroll
        for (int ni = 0; ni < 8; ni++) {
            mx0 = fmaxf(mx0, fmaxf(sf[ni][0], sf[ni][1]));
            mx1 = fmaxf(mx1, fmaxf(sf[ni][2], sf[ni][3]));
        }
        mx0 *= SC; mx1 *= SC;
        mx0 = fmaxf(mx0, __shfl_xor_sync(~0u, mx0, 1));
        mx0 = fmaxf(mx0, __shfl_xor_sync(~0u, mx0, 2));
        mx1 = fmaxf(mx1, __shfl_xor_sync(~0u, mx1, 1));
        mx1 = fmaxf(mx1, __shfl_xor_sync(~0u, mx1, 2));

        const float mn0 = fmaxf(m0, mx0), mn1 = fmaxf(m1, mx1);
        const float c0f = __expf(m0 - mn0), c1f = __expf(m1 - mn1);
        m0 = mn0; m1 = mn1;
        l0 *= c0f; l1 *= c1f;
#pragma unroll
        for (int no = 0; no < 8; no++) {
            oa[no][0] *= c0f; oa[no][1] *= c0f;
            oa[no][2] *= c1f; oa[no][3] *= c1f;
        }

        uint32_t af[4][4];
        float sum0 = 0.f, sum1 = 0.f;
#pragma unroll
        for (int ni = 0; ni < 8; ni++) {
            half2 p0 = h2exp2(__floats2half2_rn((sf[ni][0] * SC - m0) * L2E,
                                                (sf[ni][1] * SC - m0) * L2E));
            half2 p1 = h2exp2(__floats2half2_rn((sf[ni][2] * SC - m1) * L2E,
                                                (sf[ni][3] * SC - m1) * L2E));
            float2 f0 = __half22float2(p0); sum0 += f0.x + f0.y;
            float2 f1 = __half22float2(p1); sum1 += f1.x + f1.y;
            const int ki = ni >> 1;
            if ((ni & 1) == 0) { af[ki][0] = h2_u32(p0); af[ki][1] = h2_u32(p1); }
            else               { af[ki][2] = h2_u32(p0); af[ki][3] = h2_u32(p1); }
        }
        l0 += sum0; l1 += sum1;

#pragma unroll
        for (int ki = 0; ki < 4; ki++) {
#pragma unroll
            for (int no = 0; no < 8; no++) {
                const half* vr = &sv[(no * 8 + g) * QPAD + 2 * tig];
                uint32_t b0 = *(const uint32_t*)(vr + 8 * ((2 * ki) ^ no));
                uint32_t b1 = *(const uint32_t*)(vr + 8 * ((2 * ki + 1) ^ no));
                mma16n8k16(oa[no], af[ki][0], af[ki][1], af[ki][2], af[ki][3], b0, b1);
            }
        }
    }

    l0 += __shfl_xor_sync(~0u, l0, 1); l0 += __shfl_xor_sync(~0u, l0, 2);
    l1 += __shfl_xor_sync(~0u, l1, 1); l1 += __shfl_xor_sync(~0u, l1, 2);
    const float inv0 = 1.f / l0, inv1 = 1.f / l1;

    const int row0 = base_q + wq * 16 + g;
#pragma unroll
    for (int no = 0; no < 8; no++) {
        const int n = hoff + no * 8 + 2 * tig;
        store2(&Op[(size_t)row0 * DMODEL + n], oa[no][0] * inv0, oa[no][1] * inv0);
        store2(&Op[(size_t)(row0 + 8) * DMODEL + n], oa[no][2] * inv1, oa[no][3] * inv1);
    }
}

// ---------------- LayerNorm: one row per CTA, 256 threads -----------------------
template<typename OutT>
__global__ void __launch_bounds__(256)
ln_kernel(const float* __restrict__ X, const float* __restrict__ gam,
          const float* __restrict__ bet, OutT* __restrict__ Y)
{
    const int row = blockIdx.x;
    const int t   = threadIdx.x;
    const int lane = t & 31, wid = t >> 5;
    const float* x = X + (size_t)row * DMODEL;

    float v0 = x[t], v1 = x[t + 256], v2 = x[t + 512];
    float s = v0 + v1 + v2;

    __shared__ float sbuf[8];
    __shared__ float s_mu, s_rstd;

#pragma unroll
    for (int o = 16; o > 0; o >>= 1) s += __shfl_xor_sync(~0u, s, o);
    if (lane == 0) sbuf[wid] = s;
    __syncthreads();
    if (t == 0) {
        float tot = 0.f;
        for (int i = 0; i < 8; i++) tot += sbuf[i];
        s_mu = tot * (1.0f / DMODEL);
    }
    __syncthreads();
    const float mu = s_mu;

    float d0 = v0 - mu, d1 = v1 - mu, d2 = v2 - mu;
    float qv = d0 * d0 + d1 * d1 + d2 * d2;
#pragma unroll
    for (int o = 16; o > 0; o >>= 1) qv += __shfl_xor_sync(~0u, qv, o);
    if (lane == 0) sbuf[wid] = qv;
    __syncthreads();
    if (t == 0) {
        float tot = 0.f;
        for (int i = 0; i < 8; i++) tot += sbuf[i];
        s_rstd = rsqrtf(tot * (1.0f / DMODEL) + LN_EPS);
    }
    __syncthreads();
    const float rstd = s_rstd;

    Y[(size_t)row * DMODEL + t      ] = (OutT)(d0 * rstd * gam[t      ] + bet[t      ]);
    Y[(size_t)row * DMODEL + t + 256] = (OutT)(d1 * rstd * gam[t + 256] + bet[t + 256]);
    Y[(size_t)row * DMODEL + t + 512] = (OutT)(d2 * rstd * gam[t + 512] + bet[t + 512]);
}

// ---------------- launch --------------------------------------------------------
extern "C" void kernel_launch(void* const* d_in, const int* in_sizes, int n_in,
                              void* d_out, int out_size)
{
    const float* x    = (const float*)d_in[0];
    const float* x1   = (const float*)d_in[1];
    const float* Wq   = (const float*)d_in[2];
    const float* bq   = (const float*)d_in[3];
    const float* Wk   = (const float*)d_in[4];
    const float* bk   = (const float*)d_in[5];
    const float* Wv   = (const float*)d_in[6];
    const float* bv   = (const float*)d_in[7];
    const float* Wo   = (const float*)d_in[8];
    const float* bo   = (const float*)d_in[9];
    const float* W1   = (const float*)d_in[10];
    const float* b1   = (const float*)d_in[11];
    const float* W2   = (const float*)d_in[12];
    const float* b2   = (const float*)d_in[13];
    const float* ln1g = (const float*)d_in[14];
    const float* ln1b = (const float*)d_in[15];
    const float* ln2g = (const float*)d_in[16];
    const float* ln2b = (const float*)d_in[17];
    float* out = (float*)d_out;

    half *xh, *x1h, *qh, *kh, *vh, *oh, *h2h, *fh;
    half *wqh, *wkh, *wvh, *woh, *w1h, *w2h;
    float *h, *tbuf;
    cudaGetSymbolAddress((void**)&xh,  g_xh);
    cudaGetSymbolAddress((void**)&x1h, g_x1h);
    cudaGetSymbolAddress((void**)&qh,  g_qh);
    cudaGetSymbolAddress((void**)&kh,  g_kh);
    cudaGetSymbolAddress((void**)&vh,  g_vh);
    cudaGetSymbolAddress((void**)&oh,  g_oh);
    cudaGetSymbolAddress((void**)&h2h, g_h2h);
    cudaGetSymbolAddress((void**)&fh,  g_fh);
    cudaGetSymbolAddress((void**)&h,   g_h);
    cudaGetSymbolAddress((void**)&tbuf,g_t);
    cudaGetSymbolAddress((void**)&wqh, g_wqh);
    cudaGetSymbolAddress((void**)&wkh, g_wkh);
    cudaGetSymbolAddress((void**)&wvh, g_wvh);
    cudaGetSymbolAddress((void**)&woh, g_woh);
    cudaGetSymbolAddress((void**)&w1h, g_w1h);
    cudaGetSymbolAddress((void**)&w2h, g_w2h);

    cudaFuncSetAttribute(qkv_gemm, cudaFuncAttributeMaxDynamicSharedMemorySize, SMEM_BY);
    cudaFuncSetAttribute(gemm_h<float>, cudaFuncAttributeMaxDynamicSharedMemorySize, SMEM_BY);
    cudaFuncSetAttribute(gemm_h<half>,  cudaFuncAttributeMaxDynamicSharedMemorySize, SMEM_BY);

    // merged one-time fp32 -> fp16 converts
    {
        CvtArgs ca;
        ca.in[0] = x;  ca.out[0] = xh;  ca.n4[0] = NTOK * DMODEL / 4;
        ca.in[1] = x1; ca.out[1] = x1h; ca.n4[1] = NTOK * DMODEL / 4;
        ca.in[2] = Wq; ca.out[2] = wqh; ca.n4[2] = DMODEL * DMODEL / 4;
        ca.in[3] = Wk; ca.out[3] = wkh; ca.n4[3] = DMODEL * DMODEL / 4;
        ca.in[4] = Wv; ca.out[4] = wvh; ca.n4[4] = DMODEL * DMODEL / 4;
        ca.in[5] = Wo; ca.out[5] = woh; ca.n4[5] = DMODEL * DMODEL / 4;
        ca.in[6] = W1; ca.out[6] = w1h; ca.n4[6] = DFFN * DMODEL / 4;
        ca.in[7] = W2; ca.out[7] = w2h; ca.n4[7] = DMODEL * DFFN / 4;
        cvt_all<<<dim3(128, 8), 256>>>(ca);
    }

    dim3 blk(256);

    // merged Q/K/V projections (CTA tile 128x128)
    qkv_gemm<<<dim3(DMODEL / 128, NTOK / 128, 3), blk, SMEM_BY>>>(
        xh, x1h, wqh, wkh, wvh, bq, bk, bv, qh, kh, vh);

    attn_mma<<<dim3(SEQ / 128, NH, NBATCH), 256>>>(qh, kh, vh, oh);

    // output projection + residual -> h (fp32)
    gemm_h<float><<<dim3(DMODEL / 128, NTOK / 128), blk, SMEM_BY>>>(
        oh, woh, bo, x, h, DMODEL, DMODEL, 1);

    // h2 = LN(h, ln2) -> fp16
    ln_kernel<half><<<NTOK, 256>>>(h, ln2g, ln2b, h2h);

    // FFN1: GELU -> fp16
    gemm_h<half><<<dim3(DFFN / 128, NTOK / 128), blk, SMEM_BY>>>(
        h2h, w1h, b1, nullptr, fh, DFFN, DMODEL, 2);

    // FFN2: + residual h -> fp32
    gemm_h<float><<<dim3(DMODEL / 128, NTOK / 128), blk, SMEM_BY>>>(
        fh, w2h, b2, h, tbuf, DMODEL, DFFN, 1);

    // out = LN(h + ffn, ln1) -> fp32
    ln_kernel<float><<<NTOK, 256>>>(tbuf, ln1g, ln1b, out);
}